// round 15
// baseline (speedup 1.0000x reference)
#include <cuda_runtime.h>
#include <cuda_bf16.h>
#include <cstdint>

#define EPSF 1e-8f
static constexpr int B_  = 8;
static constexpr int N_  = 256;
static constexpr int NF_ = 2048;

__device__ __nv_bfloat16 g_K[B_ * N_ * N_];   // bf16 K, L2-resident
__device__ float g_rsK[B_ * N_];              // rowsum(K)
__device__ float g_cpr[B_ * N_];              // raw coupling sum: Σ_j K_ij sin(...)
__device__ int   g_conv[B_];                  // 1 = some certificate failed

#define GRIDDEP_WAIT() asm volatile("griddepcontrol.wait;" ::: "memory")

// ---------------------------------------------------------------------------
// helpers
// ---------------------------------------------------------------------------
__device__ __forceinline__ void unpack8(uint4 kr, float* f)
{
    float2 f0 = __bfloat1622float2(*reinterpret_cast<__nv_bfloat162*>(&kr.x));
    float2 f1 = __bfloat1622float2(*reinterpret_cast<__nv_bfloat162*>(&kr.y));
    float2 f2 = __bfloat1622float2(*reinterpret_cast<__nv_bfloat162*>(&kr.z));
    float2 f3 = __bfloat1622float2(*reinterpret_cast<__nv_bfloat162*>(&kr.w));
    f[0] = f0.x; f[1] = f0.y; f[2] = f1.x; f[3] = f1.y;
    f[4] = f2.x; f[5] = f2.y; f[6] = f3.x; f[7] = f3.y;
}

__device__ __forceinline__ float dot8(uint4 kr, const float* vj)
{
    float kf[8];
    unpack8(kr, kf);
    float acc = 0.f;
#pragma unroll
    for (int x = 0; x < 8; ++x) acc = fmaf(kf[x], vj[x], acc);
    return acc;
}

// 256-thread broadcast sum
__device__ __forceinline__ float blk_sum256(float val, float* red)
{
#pragma unroll
    for (int o = 16; o; o >>= 1) val += __shfl_xor_sync(0xffffffffu, val, o);
    if ((threadIdx.x & 31) == 0) red[threadIdx.x >> 5] = val;
    __syncthreads();
    if (threadIdx.x < 32) {
        float s = (threadIdx.x < 8) ? red[threadIdx.x] : 0.f;
#pragma unroll
        for (int o = 4; o; o >>= 1) s += __shfl_xor_sync(0xffffffffu, s, o);
        if (threadIdx.x == 0) red[8] = s;
    }
    __syncthreads();
    float r = red[8];
    __syncthreads();
    return r;
}

// ---------------------------------------------------------------------------
// Kernel 1: pooling -> K row (bf16) + per-row scalars only.
//  round1: sum w;  K = (W+EPS)^10;  round2: (sum K, sum K*sin)
//  Stores g_rsK[I], g_cpr[I]. NO exp/softmax/divisions/atomics here.
// Grid (256,8), 256 threads, <=32 regs (8 CTAs/SM).
// ---------------------------------------------------------------------------
__global__ void __launch_bounds__(256, 8) pool_build_k(
    const float* __restrict__ A,
    const float* __restrict__ theta_g, const float* __restrict__ alpha_g)
{
    const int I = blockIdx.x, b = blockIdx.y;
    const int t = threadIdx.x;
    const int wd = t >> 5, lane = t & 31;
    const float* base = A + ((size_t)b * NF_ + (size_t)I * 8) * NF_;

    // small input loads (L2-resident after first touch), issued early
    float thmine = theta_g[b * N_ + t];
    float alp    = __ldg(&alpha_g[(size_t)I * N_ + t]);

    __shared__ float rA[9], rC[9], rD[9];
    __shared__ float stI;
    if (t == I) stI = thmine;                       // broadcast theta_I

    // direct block-column accumulation: cols [8t, 8t+8) over 8 rows
    const float4* rp = reinterpret_cast<const float4*>(base) + 2 * t;
    float acc0 = 0.f, acc1 = 0.f;
#pragma unroll
    for (int r = 0; r < 8; ++r) {
        float4 f0 = __ldcs(rp + (size_t)r * 512);
        float4 f1 = __ldcs(rp + (size_t)r * 512 + 1);
        acc0 += (f0.x + f0.y) + (f0.z + f0.w);
        acc1 += (f1.x + f1.y) + (f1.z + f1.w);
    }
    float w = fmaxf((acc0 + acc1) * (1.0f / 64.0f), 0.0f);   // relu(A_lat[I,t])

    // ---- round 1: sum w ----
    {
        float sv = w;
#pragma unroll
        for (int o = 16; o; o >>= 1) sv += __shfl_xor_sync(0xffffffffu, sv, o);
        if (lane == 0) rA[wd] = sv;
    }
    __syncthreads();
    if (t < 32) {
        float s = (t < 8) ? rA[t] : 0.f;
#pragma unroll
        for (int o = 4; o; o >>= 1) s += __shfl_xor_sync(0xffffffffu, s, o);
        if (t == 0) rA[8] = s;
    }
    __syncthreads();
    const float rowsum = rA[8];
    const float tI = stI;

    float W = (rowsum > EPSF) ? (w / (rowsum + EPSF)) : (1.0f / N_);
    float x  = W + EPSF;
    float x2 = x * x, x4 = x2 * x2, x8 = x4 * x4;
    __nv_bfloat16 kb = __float2bfloat16(x8 * x2);   // K = x^10 (bf16)
    g_K[((size_t)b * N_ + I) * N_ + t] = kb;

    float kf = __bfloat162float(kb);
    float sn = kf * __sinf(thmine - tI - alp);      // K_It * sin(th_t - th_I - a_It)

    // ---- round 2: (sum K, sum sin-term) ----
    {
        float sv = kf, cv = sn;
#pragma unroll
        for (int o = 16; o; o >>= 1) {
            sv += __shfl_xor_sync(0xffffffffu, sv, o);
            cv += __shfl_xor_sync(0xffffffffu, cv, o);
        }
        if (lane == 0) { rC[wd] = sv; rD[wd] = cv; }
    }
    __syncthreads();
    if (t == 0) {
        float rsK = 0.f, cps = 0.f;
#pragma unroll
        for (int i = 0; i < 8; ++i) { rsK += rC[i]; cps += rD[i]; }
        g_rsK[b * N_ + I] = rsK;
        g_cpr[b * N_ + I] = cps;
    }
}

// ---------------------------------------------------------------------------
// Kernel 2 (kmid2): per-batch Sinkhorn closed form + exact certificates +
// fast-path output. Grid (8 colgroups, 8 batch) = 64 CTAs, 256 thr.
// Prolog (overlapped with pool via PDL): softmax p from gamma, per-col scalars.
// Post-wait: u1/u2 from g_rsK (pointwise), S = blk_sum(u2*kv1), row check,
// exact column cert (KTu_j + EPS == EPS), outputs from u2/cpr/S.
// ---------------------------------------------------------------------------
__global__ void __launch_bounds__(256) kmid2(
    const float* __restrict__ theta_g, const float* __restrict__ gamma_g,
    const float* __restrict__ omega_g, const float* __restrict__ logk_g,
    float* __restrict__ out)
{
    __shared__ float p_s[256];
    __shared__ float u1_s[256];
    __shared__ float u2_s[256];
    __shared__ float red[10];
    __shared__ float part[8][33];                  // padded: conflict-free col read

    const int g = blockIdx.x, b = blockIdx.y;
    const int t = threadIdx.x;
    const int w = t >> 5, l = t & 31;
    const int j = g * 32 + l;

    // ---- prolog: pure-input work (overlaps pool under PDL) ----
    float e = expf(gamma_g[b * N_ + t]);           // no-max softmax
    float ti = 0.f, ga = 0.f, om = 0.f, kap = 0.f;
    if (t < 32) {
        ti  = theta_g[b * N_ + j];
        ga  = gamma_g[b * N_ + j];
        om  = omega_g[j];
        kap = log1pf(expf(logk_g[j]));             // softplus
    }
    float esum = blk_sum256(e, red);
    p_s[t] = e / esum;

    GRIDDEP_WAIT();                                 // wait for pool (PDL)

    // ---- pointwise Sinkhorn closed form from rsK ----
    const float q  = 1.0f / N_;
    const float v1 = q / EPSF;                      // uniform v1 (certified below)
    float rsK = g_rsK[b * N_ + t];
    float u1  = p_s[t] / (rsK * q + EPSF);          // true first u (Kv0 = rsK/256)
    float kv1 = v1 * rsK;
    float u2  = p_s[t] / (kv1 + EPSF);
    u1_s[t] = u1;
    u2_s[t] = u2;
    // row fixed-point check (all threads; idempotent write)
    if (u2 != u1) g_conv[b] = 1;

    float S = blk_sum256(u2 * kv1, red);            // deterministic order

    // ---- exact column certificate: KTu_j over rows [32w, 32w+32) ----
    const __nv_bfloat16* kcol = g_K + (size_t)b * N_ * N_ + j;
    float acc = 0.f;
#pragma unroll
    for (int k = 0; k < 32; ++k) {
        int i = w * 32 + k;
        acc = fmaf(__bfloat162float(__ldg(kcol + (size_t)i * N_)), u1_s[i], acc);
    }
    part[w][l] = acc;
    __syncthreads();

    if (t < 32) {
        float ktu = 0.f;
#pragma unroll
        for (int r = 0; r < 8; ++r) ktu += part[r][l];

        bool colfail = !(ktu + EPSF == EPSF);       // exact absorption check
        if (__any_sync(0xffffffffu, colfail) && l == 0)
            g_conv[b] = 1;

        // fast-path output (kguard overwrites if any certificate failed)
        float Sinv = 1.0f / (S + EPSF);
        float cp   = v1 * g_cpr[b * N_ + j];
        out[b * N_ + j] = ti + om + u2_s[j] * Sinv * cp + kap * (ga - ti);
    }
}

// ---------------------------------------------------------------------------
// Kernel 3 (kguard): early-exit on fast path; faithful 10-iter Sinkhorn
// fallback (overwrites outputs) if any certificate failed. Housekeeping.
// Grid 8, 256 threads, PDL.
// ---------------------------------------------------------------------------
__global__ void __launch_bounds__(256) kguard(
    const float* __restrict__ theta_g, const float* __restrict__ gamma_g,
    const float* __restrict__ omega_g, const float* __restrict__ alpha_g,
    const float* __restrict__ logk_g,  float* __restrict__ out)
{
    __shared__ float red[10];
    __shared__ float vsh[256], tsh[256], p_s[256], u_s[256], kv_s[256];

    const int b = blockIdx.x;
    const int t = threadIdx.x;

    GRIDDEP_WAIT();                                 // wait for kmid2 (PDL)

    const int conv = g_conv[b];

    if (conv != 0) {
        // -------- fallback: faithful 10-iter Sinkhorn from scratch --------
        float ti  = theta_g[b * N_ + t];
        float ga  = gamma_g[b * N_ + t];
        float om  = omega_g[t];
        float kap = log1pf(expf(logk_g[t]));        // softplus

        // softmax p (same no-max form as fast path)
        float e = expf(ga);
        float esum = blk_sum256(e, red);

        const int wd = t >> 5, lane = t & 31;
        p_s[t] = e / esum;
        u_s[t] = 1.0f / N_;
        vsh[t] = 1.0f / N_;
        tsh[t] = ti;
        __syncthreads();

        for (int it = 0; it < 10; ++it) {
            // u-update: 8 warps x 32 rows, K from L2
#pragma unroll 1
            for (int k = 0; k < 32; ++k) {
                int ii = wd * 32 + k;
                uint4 kr = reinterpret_cast<const uint4*>(g_K + ((size_t)b * N_ + ii) * N_)[lane];
                float acc = dot8(kr, &vsh[lane * 8]);
#pragma unroll
                for (int o = 16; o; o >>= 1) acc += __shfl_xor_sync(0xffffffffu, acc, o);
                if (lane == 0) u_s[ii] = p_s[ii] / (acc + EPSF);
            }
            __syncthreads();
            // v-update: thread t = column j
            float s = 0.f;
#pragma unroll 1
            for (int ii = 0; ii < N_; ++ii)
                s = fmaf(__bfloat162float(g_K[((size_t)b * N_ + ii) * N_ + t]), u_s[ii], s);
            __syncthreads();
            vsh[t] = (1.0f / N_) / (s + EPSF);
            __syncthreads();
        }

        // final Kv, S
#pragma unroll 1
        for (int k = 0; k < 32; ++k) {
            int ii = wd * 32 + k;
            uint4 kr = reinterpret_cast<const uint4*>(g_K + ((size_t)b * N_ + ii) * N_)[lane];
            float acc = dot8(kr, &vsh[lane * 8]);
#pragma unroll
            for (int o = 16; o; o >>= 1) acc += __shfl_xor_sync(0xffffffffu, acc, o);
            if (lane == 0) kv_s[ii] = acc;
        }
        __syncthreads();
        float S = blk_sum256(u_s[t] * kv_s[t], red);
        float Sinv = 1.0f / (S + EPSF);

        // coupling: thread t = row i
        float acc = 0.f;
#pragma unroll 1
        for (int j = 0; j < N_; ++j) {
            float kv = __bfloat162float(g_K[((size_t)b * N_ + t) * N_ + j]) * vsh[j];
            float d  = tsh[j] - ti - alpha_g[(size_t)t * N_ + j];
            acc = fmaf(kv, __sinf(d), acc);
        }
        float td = om + u_s[t] * Sinv * acc + kap * (ga - ti);
        out[b * N_ + t] = ti + td;
        __syncthreads();
    }

    // -------- housekeeping for next graph replay --------
    if (t == 0) g_conv[b] = 0;
}

// ---------------------------------------------------------------------------
extern "C" void kernel_launch(void* const* d_in, const int* in_sizes, int n_in,
                              void* d_out, int out_size)
{
    const float* theta = (const float*)d_in[0];
    const float* gamma = (const float*)d_in[1];
    const float* A     = (const float*)d_in[2];
    const float* omega = (const float*)d_in[3];
    const float* alpha = (const float*)d_in[4];
    const float* logk  = (const float*)d_in[5];
    float* out = (float*)d_out;

    dim3 g1(256, 8);
    pool_build_k<<<g1, 256>>>(A, theta, alpha);

    // kmid2 with PDL: prolog (softmax etc.) overlaps pool
    {
        cudaLaunchConfig_t cfg = {};
        cfg.gridDim  = dim3(8, 8);
        cfg.blockDim = dim3(256);
        cudaLaunchAttribute at[1];
        at[0].id = cudaLaunchAttributeProgrammaticStreamSerialization;
        at[0].val.programmaticStreamSerializationAllowed = 1;
        cfg.attrs = at;
        cfg.numAttrs = 1;
        cudaLaunchKernelEx(&cfg, kmid2, theta, gamma, omega, logk, out);
    }

    // kguard with PDL: near-empty on fast path
    {
        cudaLaunchConfig_t cfg = {};
        cfg.gridDim  = dim3(B_);
        cfg.blockDim = dim3(256);
        cudaLaunchAttribute at[1];
        at[0].id = cudaLaunchAttributeProgrammaticStreamSerialization;
        at[0].val.programmaticStreamSerializationAllowed = 1;
        cfg.attrs = at;
        cfg.numAttrs = 1;
        cudaLaunchKernelEx(&cfg, kguard, theta, gamma, omega, alpha, logk, out);
    }
}